// round 11
// baseline (speedup 1.0000x reference)
#include <cuda_runtime.h>
#include <cuda_bf16.h>
#include <cstdint>

// ---------------- problem constants ----------------
#define BB    128
#define QLQ   32
#define DLD   1024
#define HH    768
#define DIMD  128
#define KC    128         // K elements per chunk
#define NCHUNK 6          // 768 / 128
#define NTILE 8           // 1024 / 128
#define NEGV  (-100000.0f)
#define NTHREADS 512

// padded smem strides (bf16 elements): 136*2=272B = 68 words ≡ +4 banks/row
#define STRK  136         // stage tiles (128 K-cols + 8 pad)
#define STRD  136         // D/Q tiles

// k_dscore smem layout (byte offsets) — TWO stages of (A,W), KC=128
#define OFF_S0A  0u                    // 128 x STRK bf16 = 34816
#define OFF_S0W  34816u                // 34816
#define OFF_S1A  69632u
#define OFF_S1W  104448u               // stages end 139264
#define OFF_D    0u                    // D tile 34816 (overlays stage0 A)
#define OFF_Q    139264u               // 32 x STRD bf16 = 8704   (end 147968)
#define OFF_N    147968u               // 128 x 4 float  = 2048   (end 150016)
#define OFF_R    150016u               // 8 x 32 float   = 1024   (end 151040)
#define SMEM_DS  151040

// k_qproj smem layout (32-row A tiles)
#define QP_S0A   0u                    // 32 x STRK bf16 = 8704
#define QP_S0W   8704u                 // 34816
#define QP_S1A   43520u
#define QP_S1W   52224u                // end 87040
#define QP_N     87040u                // 32 x 8 float = 1024
#define SMEM_QP  88064

// ---------------- device scratch ----------------
__device__ __align__(16) __nv_bfloat16 g_Wb[DIMD * HH];          // 192 KB
__device__ __align__(16) __nv_bfloat16 g_Qb[BB * QLQ * DIMD];    // 1 MB
__device__ float g_part[BB * NTILE * QLQ];                       // 128 KB

// ---------------- helpers ----------------
static __device__ __forceinline__ uint32_t smem_u32(const void* p) {
    uint32_t a;
    asm("{ .reg .u64 t; cvta.to.shared.u64 t, %1; cvt.u32.u64 %0, t; }"
        : "=r"(a) : "l"(p));
    return a;
}
static __device__ __forceinline__ void ldsm_x4(uint32_t (&r)[4], uint32_t addr) {
    asm volatile("ldmatrix.sync.aligned.m8n8.x4.shared.b16 {%0,%1,%2,%3}, [%4];"
                 : "=r"(r[0]), "=r"(r[1]), "=r"(r[2]), "=r"(r[3]) : "r"(addr));
}
static __device__ __forceinline__ void mma_bf16(float (&d)[4], const uint32_t (&a)[4],
                                                const uint32_t* b) {
    asm volatile("mma.sync.aligned.m16n8k16.row.col.f32.bf16.bf16.f32 "
                 "{%0,%1,%2,%3}, {%4,%5,%6,%7}, {%8,%9}, {%0,%1,%2,%3};"
                 : "+f"(d[0]), "+f"(d[1]), "+f"(d[2]), "+f"(d[3])
                 : "r"(a[0]), "r"(a[1]), "r"(a[2]), "r"(a[3]), "r"(b[0]), "r"(b[1]));
}
static __device__ __forceinline__ uint32_t packbf2(float lo, float hi) {
    __nv_bfloat162 v = __floats2bfloat162_rn(lo, hi);
    return *reinterpret_cast<uint32_t*>(&v);
}
static __device__ __forceinline__ void cp16(uint32_t dst, const void* src) {
    asm volatile("cp.async.cg.shared.global [%0], [%1], 16;"
                 :: "r"(dst), "l"(src) : "memory");
}
#define CP_COMMIT() asm volatile("cp.async.commit_group;" ::: "memory")
#define CP_WAIT0()  asm volatile("cp.async.wait_group 0;" :: : "memory")

static __device__ __forceinline__ void sts128(uint32_t dst, uint32_t a, uint32_t b,
                                              uint32_t c, uint32_t d) {
    asm volatile("st.shared.v4.b32 [%0], {%1, %2, %3, %4};"
                 :: "r"(dst), "r"(a), "r"(b), "r"(c), "r"(d) : "memory");
}

// stage 32 fp32 (af[8]) as 32 bf16: groups i=0,1 at +i*128B, two v4 each.
// bank walk per phase: {0-3,8-11,16-19,24-27} (+4/row) -> conflict-free.
static __device__ __forceinline__ void stage_A32(uint32_t dst, const float4 (&af)[8]) {
#pragma unroll
    for (int i = 0; i < 2; ++i) {
        sts128(dst + (uint32_t)(i * 128),
               packbf2(af[4 * i].x, af[4 * i].y),     packbf2(af[4 * i].z, af[4 * i].w),
               packbf2(af[4 * i + 1].x, af[4 * i + 1].y), packbf2(af[4 * i + 1].z, af[4 * i + 1].w));
        sts128(dst + (uint32_t)(i * 128 + 16),
               packbf2(af[4 * i + 2].x, af[4 * i + 2].y), packbf2(af[4 * i + 2].z, af[4 * i + 2].w),
               packbf2(af[4 * i + 3].x, af[4 * i + 3].y), packbf2(af[4 * i + 3].z, af[4 * i + 3].w));
    }
}

// ---------------- kernel 0: W -> bf16 ----------------
__global__ void k_prep(const float* __restrict__ W) {
    int i = blockIdx.x * blockDim.x + threadIdx.x;
    if (i < DIMD * HH) g_Wb[i] = __float2bfloat16(W[i]);
}

// ---------------- kernel 1: Q projection (1 CTA per batch, 32 rows) ----------------
__global__ void __launch_bounds__(NTHREADS) k_qproj(const float* __restrict__ Q_emb) {
    extern __shared__ char dyn[];
    uint32_t sb = smem_u32(dyn);
    const int tid = threadIdx.x, lane = tid & 31, w = tid >> 5;
    const int wmq = w & 1, wnq = w >> 1;           // m-tile (16), n-group (16 cols)
    const int b = blockIdx.x;

    const float* a_rows = Q_emb + (size_t)b * QLQ * HH;
    // A loads: row tid>>4 (0..31), 8 contiguous fp32 at col (tid&15)*8
    const int lrq = tid >> 4, jq = tid & 15;
    const float* aptr = a_rows + (size_t)lrq * HH + jq * 8;
    const uint32_t stOA = (uint32_t)(lrq * STRK + jq * 8) * 2;
    // W loads: row tid>>2, 32 bf16 at col (tid&3)*32, 4x cp16
    const int lrw = tid >> 2, jw = tid & 3;
    const __nv_bfloat16* wsrc = g_Wb + (size_t)lrw * HH + jw * 32;
    const uint32_t stOW = (uint32_t)(lrw * STRK) * 2 + (uint32_t)jw * 64;

    const uint32_t sA[2] = {sb + QP_S0A, sb + QP_S1A};
    const uint32_t sW[2] = {sb + QP_S0W, sb + QP_S1W};
    const uint32_t ldAo = (uint32_t)((wmq * 16 + (lane & 15)) * STRK + (lane >> 4) * 8) * 2;
    const uint32_t ldBo = (uint32_t)((wnq * 16 + ((lane >> 4) & 1) * 8 + (lane & 7)) * STRK
                                     + ((lane >> 3) & 1) * 8) * 2;

    float4 af2[2];
    // prologue: chunk0 -> stage0; chunk1 -> regs
    af2[0] = *(const float4*)(aptr);
    af2[1] = *(const float4*)(aptr + 4);
    sts128(sA[0] + stOA, packbf2(af2[0].x, af2[0].y), packbf2(af2[0].z, af2[0].w),
           packbf2(af2[1].x, af2[1].y), packbf2(af2[1].z, af2[1].w));
#pragma unroll
    for (int jj = 0; jj < 4; ++jj) cp16(sW[0] + stOW + jj * 16u, wsrc + jj * 8);
    CP_COMMIT();
    af2[0] = *(const float4*)(aptr + KC);
    af2[1] = *(const float4*)(aptr + KC + 4);
    CP_WAIT0();
    __syncthreads();

    float acc[2][4] = {};
    for (int kc = 0; kc < NCHUNK; ++kc) {
        const int cur = kc & 1;
        if (kc + 1 < NCHUNK) {
            const int nxt = cur ^ 1;
            sts128(sA[nxt] + stOA,
                   packbf2(af2[0].x, af2[0].y), packbf2(af2[0].z, af2[0].w),
                   packbf2(af2[1].x, af2[1].y), packbf2(af2[1].z, af2[1].w));
            const __nv_bfloat16* wp = wsrc + (kc + 1) * KC;
#pragma unroll
            for (int jj = 0; jj < 4; ++jj) cp16(sW[nxt] + stOW + jj * 16u, wp + jj * 8);
            CP_COMMIT();
            if (kc + 2 < NCHUNK) {
                af2[0] = *(const float4*)(aptr + (kc + 2) * KC);
                af2[1] = *(const float4*)(aptr + (kc + 2) * KC + 4);
            }
        }
#pragma unroll
        for (int ks = 0; ks < 8; ++ks) {
            uint32_t afr[4], bfr[4];
            ldsm_x4(afr, sA[cur] + ldAo + (uint32_t)(ks * 16) * 2);
            ldsm_x4(bfr, sW[cur] + ldBo + (uint32_t)(ks * 16) * 2);
            mma_bf16(acc[0], afr, bfr);
            mma_bf16(acc[1], afr, bfr + 2);
        }
        CP_WAIT0();
        __syncthreads();
    }

    // epilogue: norms over 8 n-groups, then normalize+store
    float* nrm = (float*)(dyn + QP_N);   // [32][8]
#pragma unroll
    for (int rs = 0; rs < 2; ++rs) {
        int gr = wmq * 16 + rs * 8 + (lane >> 2);
        float s = 0.f;
#pragma unroll
        for (int nt = 0; nt < 2; ++nt) {
            float x = acc[nt][rs * 2], y = acc[nt][rs * 2 + 1];
            s = fmaf(x, x, fmaf(y, y, s));
        }
        s += __shfl_xor_sync(0xFFFFFFFFu, s, 1);
        s += __shfl_xor_sync(0xFFFFFFFFu, s, 2);
        if ((lane & 3) == 0) nrm[gr * 8 + wnq] = s;
    }
    __syncthreads();
    if (tid < 32) {
        float s = 0.f;
#pragma unroll
        for (int k = 0; k < 8; ++k) s += nrm[tid * 8 + k];
        nrm[tid * 8] = rsqrtf(fmaxf(s, 1e-24f));
    }
    __syncthreads();
#pragma unroll
    for (int rs = 0; rs < 2; ++rs) {
        int gr = wmq * 16 + rs * 8 + (lane >> 2);
        float iv = nrm[gr * 8];
        size_t row = (size_t)b * QLQ + gr;
#pragma unroll
        for (int nt = 0; nt < 2; ++nt) {
            int col = wnq * 16 + nt * 8 + (lane & 3) * 2;
            *(uint32_t*)(g_Qb + row * DIMD + col) =
                packbf2(acc[nt][rs * 2] * iv, acc[nt][rs * 2 + 1] * iv);
        }
    }
}

// ---------------- GEMM1 mainloop (KC=128, 2-stage, 1 sync/chunk) ----------------
static __device__ __forceinline__ void gemm1(const float* __restrict__ a_rows,
                                             uint32_t sb,
                                             float (&acc)[2][4][4], int tid) {
    const int lane = tid & 31, w = tid >> 5;
    const int wm = w & 3, wn = w >> 2;
    const int lr = tid >> 2;                    // 0..127 load row
    const int lc16 = (tid & 3) * 16;            // A col base
    const int jw = tid & 3;
    const float* aptr = a_rows + (size_t)lr * HH + lc16;
    const __nv_bfloat16* wsrc = g_Wb + (size_t)lr * HH + jw * 32;

    const uint32_t sA[2] = {sb + OFF_S0A, sb + OFF_S1A};
    const uint32_t sW[2] = {sb + OFF_S0W, sb + OFF_S1W};
    const uint32_t stOA = (uint32_t)(lr * STRK + lc16) * 2;
    const uint32_t stOW = (uint32_t)(lr * STRK) * 2 + (uint32_t)jw * 64;
    const uint32_t ldAo = (uint32_t)((wm * 32 + (lane & 15)) * STRK + (lane >> 4) * 8) * 2;
    const uint32_t ldBo = (uint32_t)((wn * 32 + ((lane >> 4) & 1) * 8 + (lane & 7)) * STRK
                                     + ((lane >> 3) & 1) * 8) * 2;

    float4 af[8];
    // prologue: chunk0 staged, W0 in flight, chunk1 in regs
#pragma unroll
    for (int i = 0; i < 2; ++i)
#pragma unroll
        for (int k = 0; k < 4; ++k)
            af[4 * i + k] = *(const float4*)(aptr + i * 64 + k * 4);
    stage_A32(sA[0] + stOA, af);
#pragma unroll
    for (int jj = 0; jj < 4; ++jj) cp16(sW[0] + stOW + jj * 16u, wsrc + jj * 8);
    CP_COMMIT();
#pragma unroll
    for (int i = 0; i < 2; ++i)
#pragma unroll
        for (int k = 0; k < 4; ++k)
            af[4 * i + k] = *(const float4*)(aptr + KC + i * 64 + k * 4);
    CP_WAIT0();
    __syncthreads();

    for (int kc = 0; kc < NCHUNK; ++kc) {
        const int cur = kc & 1;
        if (kc + 1 < NCHUNK) {
            const int nxt = cur ^ 1;
            stage_A32(sA[nxt] + stOA, af);       // af = chunk kc+1
            const __nv_bfloat16* wp = wsrc + (kc + 1) * KC;
#pragma unroll
            for (int jj = 0; jj < 4; ++jj) cp16(sW[nxt] + stOW + jj * 16u, wp + jj * 8);
            CP_COMMIT();
            if (kc + 2 < NCHUNK) {
                const float* ap = aptr + (kc + 2) * KC;
#pragma unroll
                for (int i = 0; i < 2; ++i)
#pragma unroll
                    for (int k = 0; k < 4; ++k)
                        af[4 * i + k] = *(const float4*)(ap + i * 64 + k * 4);
            }
        }
        // MMA on stage cur: 8 k-steps
#pragma unroll
        for (int ks = 0; ks < 8; ++ks) {
            uint32_t afr[2][4];
#pragma unroll
            for (int mt = 0; mt < 2; ++mt)
                ldsm_x4(afr[mt], sA[cur] + ldAo + (uint32_t)(mt * 16 * STRK + ks * 16) * 2);
#pragma unroll
            for (int np = 0; np < 2; ++np) {
                uint32_t bfr[4];
                ldsm_x4(bfr, sW[cur] + ldBo + (uint32_t)(np * 16 * STRK + ks * 16) * 2);
                mma_bf16(acc[0][np * 2],     afr[0], bfr);
                mma_bf16(acc[1][np * 2],     afr[1], bfr);
                mma_bf16(acc[0][np * 2 + 1], afr[0], bfr + 2);
                mma_bf16(acc[1][np * 2 + 1], afr[1], bfr + 2);
            }
        }
        CP_WAIT0();
        __syncthreads();
    }
}

// ---------------- kernel 2: D projection + scoring ----------------
__global__ void __launch_bounds__(NTHREADS)
k_dscore(const float* __restrict__ D_emb,
         const int* __restrict__ doc_ids,
         const int* __restrict__ doc_attn) {
    extern __shared__ char dyn[];
    uint32_t sb = smem_u32(dyn);
    const int tid = threadIdx.x, lane = tid & 31, w = tid >> 5;
    const int wm = w & 3, wn = w >> 2;
    const int tile = blockIdx.x, b = blockIdx.y;

    // stage Q tile (32 x 128 bf16) into OFF_Q (disjoint from pipeline stages)
    for (int g = tid; g < 512; g += NTHREADS) {
        int qr = g >> 4, qc = (g & 15) * 8;
        uint4 v = *(const uint4*)(g_Qb + ((size_t)b * QLQ + qr) * DIMD + qc);
        *(uint4*)(dyn + OFF_Q + (qr * STRD + qc) * 2) = v;
    }

    float acc[2][4][4] = {};
    gemm1(D_emb + ((size_t)b * DLD + (size_t)tile * 128) * HH, sb, acc, tid);
    // gemm1 ends with __syncthreads: stage reads complete -> D overlay safe

    float* nrm = (float*)(dyn + OFF_N);
    const uint32_t sD = sb + OFF_D;
    // epilogue 1: row sq-sums + bf16 convert into smem D tile
#pragma unroll
    for (int mt = 0; mt < 2; ++mt)
#pragma unroll
        for (int rs = 0; rs < 2; ++rs) {
            int gr = wm * 32 + mt * 16 + rs * 8 + (lane >> 2);
            float s = 0.f;
#pragma unroll
            for (int nt = 0; nt < 4; ++nt) {
                float x = acc[mt][nt][rs * 2], y = acc[mt][nt][rs * 2 + 1];
                s = fmaf(x, x, fmaf(y, y, s));
                int col = wn * 32 + nt * 8 + (lane & 3) * 2;
                asm volatile("st.shared.b32 [%0], %1;"
                             :: "r"(sD + (uint32_t)(gr * STRD + col) * 2),
                                "r"(packbf2(x, y)) : "memory");
            }
            s += __shfl_xor_sync(0xFFFFFFFFu, s, 1);
            s += __shfl_xor_sync(0xFFFFFFFFu, s, 2);
            if ((lane & 3) == 0) nrm[gr * 4 + wn] = s;
        }
    __syncthreads();
    if (tid < 128) {
        float s = nrm[tid * 4] + nrm[tid * 4 + 1] + nrm[tid * 4 + 2] + nrm[tid * 4 + 3];
        nrm[tid * 4] = rsqrtf(fmaxf(s, 1e-24f));
    }
    __syncthreads();

    // GEMM2 (warps 0-7): [128 tokens x 32 queries] = D_tile @ Q_tile^T, K=128
    if (w < 8) {
        const uint32_t sQ = sb + OFF_Q;
        const uint32_t ldA2 = sD + (uint32_t)((w * 16 + (lane & 15)) * STRD
                                              + (lane >> 4) * 8) * 2;
        const uint32_t ldB2 = sQ + (uint32_t)((((lane >> 4) & 1) * 8 + (lane & 7)) * STRD
                                              + ((lane >> 3) & 1) * 8) * 2;
        float acc2[4][4] = {};
#pragma unroll
        for (int ks = 0; ks < 8; ++ks) {
            uint32_t afr[4];
            ldsm_x4(afr, ldA2 + (uint32_t)(ks * 16) * 2);
#pragma unroll
            for (int np = 0; np < 2; ++np) {
                uint32_t bfr[4];
                ldsm_x4(bfr, ldB2 + (uint32_t)(np * 16 * STRD + ks * 16) * 2);
                mma_bf16(acc2[np * 2],     afr, bfr);
                mma_bf16(acc2[np * 2 + 1], afr, bfr + 2);
            }
        }

        const int tb = b * DLD + tile * 128;
        const int r0 = w * 16 + (lane >> 2), r1 = r0 + 8;
        const float iv0 = nrm[r0 * 4], iv1 = nrm[r1 * 4];
        const int id0 = doc_ids[tb + r0], id1 = doc_ids[tb + r1];
        const int at0 = doc_attn[tb + r0], at1 = doc_attn[tb + r1];
        float colmax[8];
#pragma unroll
        for (int nt = 0; nt < 4; ++nt)
#pragma unroll
            for (int c = 0; c < 2; ++c) {
                float v0 = at0 ? (id0 ? fmaf(2.f * iv0, acc2[nt][c], -2.f) : -1.f) : NEGV;
                float v1 = at1 ? (id1 ? fmaf(2.f * iv1, acc2[nt][2 + c], -2.f) : -1.f) : NEGV;
                colmax[nt * 2 + c] = fmaxf(v0, v1);
            }
#pragma unroll
        for (int s = 4; s < 32; s <<= 1)
#pragma unroll
            for (int j = 0; j < 8; ++j)
                colmax[j] = fmaxf(colmax[j], __shfl_xor_sync(0xFFFFFFFFu, colmax[j], s));

        float* red = (float*)(dyn + OFF_R);
        if (lane < 4)
#pragma unroll
            for (int nt = 0; nt < 4; ++nt)
#pragma unroll
                for (int c = 0; c < 2; ++c)
                    red[w * 32 + nt * 8 + lane * 2 + c] = colmax[nt * 2 + c];
    }
    __syncthreads();
    if (tid < 32) {
        float* red = (float*)(dyn + OFF_R);
        float m = -3.0e38f;
#pragma unroll
        for (int ww = 0; ww < 8; ++ww) m = fmaxf(m, red[ww * 32 + tid]);
        g_part[((size_t)b * NTILE + tile) * QLQ + tid] = m;
    }
}

// ---------------- kernel 3: combine tiles -> out[B] ----------------
__global__ void k_final(float* __restrict__ out) {
    int b = blockIdx.x, q = threadIdx.x;
    float m = -3.0e38f;
#pragma unroll
    for (int t = 0; t < NTILE; ++t)
        m = fmaxf(m, g_part[((size_t)b * NTILE + t) * QLQ + q]);
#pragma unroll
    for (int s = 16; s > 0; s >>= 1)
        m += __shfl_xor_sync(0xFFFFFFFFu, m, s);
    if (q == 0) out[b] = m;
}

// ---------------- launch ----------------
extern "C" void kernel_launch(void* const* d_in, const int* in_sizes, int n_in,
                              void* d_out, int out_size) {
    const float* Q_emb = (const float*)d_in[0];
    const float* D_emb = (const float*)d_in[1];
    const int*   ids   = (const int*)d_in[2];
    const int*   attn  = (const int*)d_in[3];
    const float* W     = (const float*)d_in[4];
    float* out = (float*)d_out;

    cudaFuncSetAttribute(k_qproj,  cudaFuncAttributeMaxDynamicSharedMemorySize, SMEM_QP);
    cudaFuncSetAttribute(k_dscore, cudaFuncAttributeMaxDynamicSharedMemorySize, SMEM_DS);

    k_prep<<<(DIMD * HH + 255) / 256, 256>>>(W);
    k_qproj<<<BB, NTHREADS, SMEM_QP>>>(Q_emb);
    k_dscore<<<dim3(NTILE, BB), NTHREADS, SMEM_DS>>>(D_emb, ids, attn);
    k_final<<<BB, 32>>>(out);
}

// round 12
// speedup vs baseline: 1.0727x; 1.0727x over previous
#include <cuda_runtime.h>
#include <cuda_bf16.h>
#include <cstdint>

// ---------------- problem constants ----------------
#define BB    128
#define QLQ   32
#define DLD   1024
#define HH    768
#define DIMD  128
#define KC    64          // K elements per chunk (k_dscore mainloop)
#define NCHUNK 12         // 768 / 64
#define NTILE 8           // 1024 / 128
#define NEGV  (-100000.0f)
#define NTHREADS 512

// padded smem strides (bf16 elements)
#define STRA  72          // k_dscore stage tiles: 64 cols + 8 pad (144 B/row)
#define STRD  136         // D/Q tiles (128 cols + 8 pad)
#define STRK  136         // k_qproj stage tiles (128 K-cols + 8 pad)

// k_dscore smem layout (byte offsets) — THREE stages of (A,W), KC=64
#define OFF_S0A  0u
#define OFF_S0W  18432u
#define OFF_S1A  36864u
#define OFF_S1W  55296u
#define OFF_S2A  73728u
#define OFF_S2W  92160u                // stages end 110592
#define OFF_D    0u                    // D tile 128 x STRD bf16 = 34816 (overlays stage0)
#define OFF_Q    110592u               // 32 x STRD bf16 = 8704  (end 119296)
#define OFF_N    119296u               // 128 x 4 float  = 2048  (end 121344)
#define OFF_R    121344u               // 8 x 32 float   = 1024  (end 122368)
#define SMEM_DS  122368

// k_qproj smem layout (32-row A tiles, KC=128, 2-stage)
#define QP_S0A   0u                    // 32 x STRK bf16 = 8704
#define QP_S0W   8704u                 // 128 x STRK bf16 = 34816
#define QP_S1A   43520u
#define QP_S1W   52224u                // end 87040
#define QP_N     87040u                // 32 x 8 float = 1024
#define SMEM_QP  88064

// ---------------- device scratch ----------------
__device__ __align__(16) __nv_bfloat16 g_Wb[DIMD * HH];          // 192 KB
__device__ __align__(16) __nv_bfloat16 g_Qb[BB * QLQ * DIMD];    // 1 MB
__device__ float g_part[BB * NTILE * QLQ];                       // 128 KB

// ---------------- helpers ----------------
static __device__ __forceinline__ uint32_t smem_u32(const void* p) {
    uint32_t a;
    asm("{ .reg .u64 t; cvta.to.shared.u64 t, %1; cvt.u32.u64 %0, t; }"
        : "=r"(a) : "l"(p));
    return a;
}
static __device__ __forceinline__ void ldsm_x4(uint32_t (&r)[4], uint32_t addr) {
    asm volatile("ldmatrix.sync.aligned.m8n8.x4.shared.b16 {%0,%1,%2,%3}, [%4];"
                 : "=r"(r[0]), "=r"(r[1]), "=r"(r[2]), "=r"(r[3]) : "r"(addr));
}
static __device__ __forceinline__ void mma_bf16(float (&d)[4], const uint32_t (&a)[4],
                                                const uint32_t* b) {
    asm volatile("mma.sync.aligned.m16n8k16.row.col.f32.bf16.bf16.f32 "
                 "{%0,%1,%2,%3}, {%4,%5,%6,%7}, {%8,%9}, {%0,%1,%2,%3};"
                 : "+f"(d[0]), "+f"(d[1]), "+f"(d[2]), "+f"(d[3])
                 : "r"(a[0]), "r"(a[1]), "r"(a[2]), "r"(a[3]), "r"(b[0]), "r"(b[1]));
}
static __device__ __forceinline__ uint32_t packbf2(float lo, float hi) {
    __nv_bfloat162 v = __floats2bfloat162_rn(lo, hi);
    return *reinterpret_cast<uint32_t*>(&v);
}
static __device__ __forceinline__ void cp16(uint32_t dst, const void* src) {
    asm volatile("cp.async.cg.shared.global [%0], [%1], 16;"
                 :: "r"(dst), "l"(src) : "memory");
}
#define CP_COMMIT() asm volatile("cp.async.commit_group;" ::: "memory")
#define CP_WAIT(n)  asm volatile("cp.async.wait_group %0;" :: "n"(n) : "memory")

static __device__ __forceinline__ void sts128(uint32_t dst, uint32_t a, uint32_t b,
                                              uint32_t c, uint32_t d) {
    asm volatile("st.shared.v4.b32 [%0], {%1, %2, %3, %4};"
                 :: "r"(dst), "r"(a), "r"(b), "r"(c), "r"(d) : "memory");
}

// conflict-free A staging (k_dscore, 16 bf16/thread): two STS.128
static __device__ __forceinline__ void stage_A(uint32_t dst, const float4 (&af)[4]) {
    uint32_t p[8];
#pragma unroll
    for (int i = 0; i < 4; ++i) {
        p[2 * i]     = packbf2(af[i].x, af[i].y);
        p[2 * i + 1] = packbf2(af[i].z, af[i].w);
    }
    sts128(dst, p[0], p[1], p[2], p[3]);
    sts128(dst + 16u, p[4], p[5], p[6], p[7]);
}

// ---------------- kernel 0: W -> bf16 ----------------
__global__ void k_prep(const float* __restrict__ W) {
    int i = blockIdx.x * blockDim.x + threadIdx.x;
    if (i < DIMD * HH) g_Wb[i] = __float2bfloat16(W[i]);
}

// ---------------- kernel 1: Q projection (1 CTA per batch, 32 rows, KC=128) ----------------
__global__ void __launch_bounds__(NTHREADS) k_qproj(const float* __restrict__ Q_emb) {
    extern __shared__ char dyn[];
    uint32_t sb = smem_u32(dyn);
    const int tid = threadIdx.x, lane = tid & 31, w = tid >> 5;
    const int wmq = w & 1, wnq = w >> 1;           // m-tile (16), n-group (16 cols)
    const int b = blockIdx.x;

    const float* a_rows = Q_emb + (size_t)b * QLQ * HH;
    const int lrq = tid >> 4, jq = tid & 15;
    const float* aptr = a_rows + (size_t)lrq * HH + jq * 8;
    const uint32_t stOA = (uint32_t)(lrq * STRK + jq * 8) * 2;
    const int lrw = tid >> 2, jw = tid & 3;
    const __nv_bfloat16* wsrc = g_Wb + (size_t)lrw * HH + jw * 32;
    const uint32_t stOW = (uint32_t)(lrw * STRK) * 2 + (uint32_t)jw * 64;

    const uint32_t sA[2] = {sb + QP_S0A, sb + QP_S1A};
    const uint32_t sW[2] = {sb + QP_S0W, sb + QP_S1W};
    const uint32_t ldAo = (uint32_t)((wmq * 16 + (lane & 15)) * STRK + (lane >> 4) * 8) * 2;
    const uint32_t ldBo = (uint32_t)((wnq * 16 + ((lane >> 4) & 1) * 8 + (lane & 7)) * STRK
                                     + ((lane >> 3) & 1) * 8) * 2;

    float4 af2[2];
    af2[0] = *(const float4*)(aptr);
    af2[1] = *(const float4*)(aptr + 4);
    sts128(sA[0] + stOA, packbf2(af2[0].x, af2[0].y), packbf2(af2[0].z, af2[0].w),
           packbf2(af2[1].x, af2[1].y), packbf2(af2[1].z, af2[1].w));
#pragma unroll
    for (int jj = 0; jj < 4; ++jj) cp16(sW[0] + stOW + jj * 16u, wsrc + jj * 8);
    CP_COMMIT();
    af2[0] = *(const float4*)(aptr + 128);
    af2[1] = *(const float4*)(aptr + 128 + 4);
    CP_WAIT(0);
    __syncthreads();

    float acc[2][4] = {};
    for (int kc = 0; kc < 6; ++kc) {
        const int cur = kc & 1;
        if (kc + 1 < 6) {
            const int nxt = cur ^ 1;
            sts128(sA[nxt] + stOA,
                   packbf2(af2[0].x, af2[0].y), packbf2(af2[0].z, af2[0].w),
                   packbf2(af2[1].x, af2[1].y), packbf2(af2[1].z, af2[1].w));
            const __nv_bfloat16* wp = wsrc + (kc + 1) * 128;
#pragma unroll
            for (int jj = 0; jj < 4; ++jj) cp16(sW[nxt] + stOW + jj * 16u, wp + jj * 8);
            CP_COMMIT();
            if (kc + 2 < 6) {
                af2[0] = *(const float4*)(aptr + (kc + 2) * 128);
                af2[1] = *(const float4*)(aptr + (kc + 2) * 128 + 4);
            }
        }
#pragma unroll
        for (int ks = 0; ks < 8; ++ks) {
            uint32_t afr[4], bfr[4];
            ldsm_x4(afr, sA[cur] + ldAo + (uint32_t)(ks * 16) * 2);
            ldsm_x4(bfr, sW[cur] + ldBo + (uint32_t)(ks * 16) * 2);
            mma_bf16(acc[0], afr, bfr);
            mma_bf16(acc[1], afr, bfr + 2);
        }
        CP_WAIT(0);
        __syncthreads();
    }

    float* nrm = (float*)(dyn + QP_N);   // [32][8]
#pragma unroll
    for (int rs = 0; rs < 2; ++rs) {
        int gr = wmq * 16 + rs * 8 + (lane >> 2);
        float s = 0.f;
#pragma unroll
        for (int nt = 0; nt < 2; ++nt) {
            float x = acc[nt][rs * 2], y = acc[nt][rs * 2 + 1];
            s = fmaf(x, x, fmaf(y, y, s));
        }
        s += __shfl_xor_sync(0xFFFFFFFFu, s, 1);
        s += __shfl_xor_sync(0xFFFFFFFFu, s, 2);
        if ((lane & 3) == 0) nrm[gr * 8 + wnq] = s;
    }
    __syncthreads();
    if (tid < 32) {
        float s = 0.f;
#pragma unroll
        for (int k = 0; k < 8; ++k) s += nrm[tid * 8 + k];
        nrm[tid * 8] = rsqrtf(fmaxf(s, 1e-24f));
    }
    __syncthreads();
#pragma unroll
    for (int rs = 0; rs < 2; ++rs) {
        int gr = wmq * 16 + rs * 8 + (lane >> 2);
        float iv = nrm[gr * 8];
        size_t row = (size_t)b * QLQ + gr;
#pragma unroll
        for (int nt = 0; nt < 2; ++nt) {
            int col = wnq * 16 + nt * 8 + (lane & 3) * 2;
            *(uint32_t*)(g_Qb + row * DIMD + col) =
                packbf2(acc[nt][rs * 2] * iv, acc[nt][rs * 2 + 1] * iv);
        }
    }
}

// ---------------- GEMM1 mainloop (3-stage pipeline, ldsm double-buffer, KC=64) ----------------
static __device__ __forceinline__ void gemm1(const float* __restrict__ a_rows,
                                             uint32_t sb,
                                             float (&acc)[2][4][4], int tid) {
    const int lane = tid & 31, w = tid >> 5;
    const int wm = w & 3, wn = w >> 2;
    const int lr = tid >> 2;                    // 0..127 load row
    const int lc = (tid & 3) * 16;              // 0,16,32,48
    const float* aptr = a_rows + (size_t)lr * HH + lc;
    const __nv_bfloat16* wsrc = g_Wb + (size_t)lr * HH + lc;

    const uint32_t sA[3] = {sb + OFF_S0A, sb + OFF_S1A, sb + OFF_S2A};
    const uint32_t sW[3] = {sb + OFF_S0W, sb + OFF_S1W, sb + OFF_S2W};
    const uint32_t stO = (uint32_t)(lr * STRA + lc) * 2;
    const uint32_t ldAo = (uint32_t)((wm * 32 + (lane & 15)) * STRA + (lane >> 4) * 8) * 2;
    const uint32_t ldBo = (uint32_t)((wn * 32 + ((lane >> 4) & 1) * 8 + (lane & 7)) * STRA
                                     + ((lane >> 3) & 1) * 8) * 2;

    float4 af[4];
    // ---- prologue: chunks 0,1 staged; chunk 2 in regs; W0 awaited
#pragma unroll
    for (int i = 0; i < 4; ++i) af[i] = *(const float4*)(aptr + i * 4);
    stage_A(sA[0] + stO, af);
    cp16(sW[0] + stO, wsrc);
    cp16(sW[0] + stO + 16u, wsrc + 8);
    CP_COMMIT();
#pragma unroll
    for (int i = 0; i < 4; ++i) af[i] = *(const float4*)(aptr + KC + i * 4);
    stage_A(sA[1] + stO, af);
    cp16(sW[1] + stO, wsrc + KC);
    cp16(sW[1] + stO + 16u, wsrc + KC + 8);
    CP_COMMIT();
#pragma unroll
    for (int i = 0; i < 4; ++i) af[i] = *(const float4*)(aptr + 2 * KC + i * 4);
    CP_WAIT(1);
    __syncthreads();

    for (int kc = 0; kc < NCHUNK; ++kc) {
        const int cur = kc % 3;
        if (kc + 2 < NCHUNK) {
            const int ns = (kc + 2) % 3;
            stage_A(sA[ns] + stO, af);           // af holds chunk kc+2
            const __nv_bfloat16* wp = wsrc + (kc + 2) * KC;
            cp16(sW[ns] + stO, wp);
            cp16(sW[ns] + stO + 16u, wp + 8);
            CP_COMMIT();
            if (kc + 3 < NCHUNK) {
                const float* ap = aptr + (kc + 3) * KC;
#pragma unroll
                for (int i = 0; i < 4; ++i) af[i] = *(const float4*)(ap + i * 4);
            }
        }
        // ---- MMA on stage cur, ldsm double-buffered across ks
        {
            uint32_t afr[2][2][4], bfr[2][2][4];
#pragma unroll
            for (int mt = 0; mt < 2; ++mt)
                ldsm_x4(afr[0][mt], sA[cur] + ldAo + (uint32_t)(mt * 16 * STRA) * 2);
#pragma unroll
            for (int np = 0; np < 2; ++np)
                ldsm_x4(bfr[0][np], sW[cur] + ldBo + (uint32_t)(np * 16 * STRA) * 2);
#pragma unroll
            for (int ks = 0; ks < 4; ++ks) {
                const int cb = ks & 1, nb = cb ^ 1;
                if (ks < 3) {
#pragma unroll
                    for (int mt = 0; mt < 2; ++mt)
                        ldsm_x4(afr[nb][mt], sA[cur] + ldAo
                                + (uint32_t)(mt * 16 * STRA + (ks + 1) * 16) * 2);
#pragma unroll
                    for (int np = 0; np < 2; ++np)
                        ldsm_x4(bfr[nb][np], sW[cur] + ldBo
                                + (uint32_t)(np * 16 * STRA + (ks + 1) * 16) * 2);
                }
#pragma unroll
                for (int np = 0; np < 2; ++np) {
                    mma_bf16(acc[0][np * 2],     afr[cb][0], bfr[cb][np]);
                    mma_bf16(acc[1][np * 2],     afr[cb][1], bfr[cb][np]);
                    mma_bf16(acc[0][np * 2 + 1], afr[cb][0], bfr[cb][np] + 2);
                    mma_bf16(acc[1][np * 2 + 1], afr[cb][1], bfr[cb][np] + 2);
                }
            }
        }
        if (kc + 2 < NCHUNK) CP_WAIT(1); else CP_WAIT(0);
        __syncthreads();
    }
}

// ---------------- kernel 2: D projection + scoring ----------------
__global__ void __launch_bounds__(NTHREADS)
k_dscore(const float* __restrict__ D_emb,
         const int* __restrict__ doc_ids,
         const int* __restrict__ doc_attn) {
    extern __shared__ char dyn[];
    uint32_t sb = smem_u32(dyn);
    const int tid = threadIdx.x, lane = tid & 31, w = tid >> 5;
    const int wm = w & 3, wn = w >> 2;
    const int tile = blockIdx.x, b = blockIdx.y;

    // stage Q tile (32 x 128 bf16) into OFF_Q (disjoint from pipeline stages)
    for (int g = tid; g < 512; g += NTHREADS) {
        int qr = g >> 4, qc = (g & 15) * 8;
        uint4 v = *(const uint4*)(g_Qb + ((size_t)b * QLQ + qr) * DIMD + qc);
        *(uint4*)(dyn + OFF_Q + (qr * STRD + qc) * 2) = v;
    }

    float acc[2][4][4] = {};
    gemm1(D_emb + ((size_t)b * DLD + (size_t)tile * 128) * HH, sb, acc, tid);
    // gemm1 ends with __syncthreads: all stage reads complete -> D overlay safe

    float* nrm = (float*)(dyn + OFF_N);
    const uint32_t sD = sb + OFF_D;
#pragma unroll
    for (int mt = 0; mt < 2; ++mt)
#pragma unroll
        for (int rs = 0; rs < 2; ++rs) {
            int gr = wm * 32 + mt * 16 + rs * 8 + (lane >> 2);
            float s = 0.f;
#pragma unroll
            for (int nt = 0; nt < 4; ++nt) {
                float x = acc[mt][nt][rs * 2], y = acc[mt][nt][rs * 2 + 1];
                s = fmaf(x, x, fmaf(y, y, s));
                int col = wn * 32 + nt * 8 + (lane & 3) * 2;
                asm volatile("st.shared.b32 [%0], %1;"
                             :: "r"(sD + (uint32_t)(gr * STRD + col) * 2),
                                "r"(packbf2(x, y)) : "memory");
            }
            s += __shfl_xor_sync(0xFFFFFFFFu, s, 1);
            s += __shfl_xor_sync(0xFFFFFFFFu, s, 2);
            if ((lane & 3) == 0) nrm[gr * 4 + wn] = s;
        }
    __syncthreads();
    if (tid < 128) {
        float s = nrm[tid * 4] + nrm[tid * 4 + 1] + nrm[tid * 4 + 2] + nrm[tid * 4 + 3];
        nrm[tid * 4] = rsqrtf(fmaxf(s, 1e-24f));
    }
    __syncthreads();

    // GEMM2 (warps 0-7): [128 tokens x 32 queries] = D_tile @ Q_tile^T, K=128
    if (w < 8) {
        const uint32_t sQ = sb + OFF_Q;
        const uint32_t ldA2 = sD + (uint32_t)((w * 16 + (lane & 15)) * STRD
                                              + (lane >> 4) * 8) * 2;
        const uint32_t ldB2 = sQ + (uint32_t)((((lane >> 4) & 1) * 8 + (lane & 7)) * STRD
                                              + ((lane >> 3) & 1) * 8) * 2;
        float acc2[4][4] = {};
#pragma unroll
        for (int ks = 0; ks < 8; ++ks) {
            uint32_t afr[4];
            ldsm_x4(afr, ldA2 + (uint32_t)(ks * 16) * 2);
#pragma unroll
            for (int np = 0; np < 2; ++np) {
                uint32_t bfr[4];
                ldsm_x4(bfr, ldB2 + (uint32_t)(np * 16 * STRD + ks * 16) * 2);
                mma_bf16(acc2[np * 2],     afr, bfr);
                mma_bf16(acc2[np * 2 + 1], afr, bfr + 2);
            }
        }

        const int tb = b * DLD + tile * 128;
        const int r0 = w * 16 + (lane >> 2), r1 = r0 + 8;
        const float iv0 = nrm[r0 * 4], iv1 = nrm[r1 * 4];
        const int id0 = doc_ids[tb + r0], id1 = doc_ids[tb + r1];
        const int at0 = doc_attn[tb + r0], at1 = doc_attn[tb + r1];
        float colmax[8];
#pragma unroll
        for (int nt = 0; nt < 4; ++nt)
#pragma unroll
            for (int c = 0; c < 2; ++c) {
                float v0 = at0 ? (id0 ? fmaf(2.f * iv0, acc2[nt][c], -2.f) : -1.f) : NEGV;
                float v1 = at1 ? (id1 ? fmaf(2.f * iv1, acc2[nt][2 + c], -2.f) : -1.f) : NEGV;
                colmax[nt * 2 + c] = fmaxf(v0, v1);
            }
#pragma unroll
        for (int s = 4; s < 32; s <<= 1)
#pragma unroll
            for (int j = 0; j < 8; ++j)
                colmax[j] = fmaxf(colmax[j], __shfl_xor_sync(0xFFFFFFFFu, colmax[j], s));

        float* red = (float*)(dyn + OFF_R);
        if (lane < 4)
#pragma unroll
            for (int nt = 0; nt < 4; ++nt)
#pragma unroll
                for (int c = 0; c < 2; ++c)
                    red[w * 32 + nt * 8 + lane * 2 + c] = colmax[nt * 2 + c];
    }
    __syncthreads();
    if (tid < 32) {
        float* red = (float*)(dyn + OFF_R);
        float m = -3.0e38f;
#pragma unroll
        for (int ww = 0; ww < 8; ++ww) m = fmaxf(m, red[ww * 32 + tid]);
        g_part[((size_t)b * NTILE + tile) * QLQ + tid] = m;
    }
}

// ---------------- kernel 3: combine tiles -> out[B] ----------------
__global__ void k_final(float* __restrict__ out) {
    int b = blockIdx.x, q = threadIdx.x;
    float m = -3.0e38f;
#pragma unroll
    for (int t = 0; t < NTILE; ++t)
        m = fmaxf(m, g_part[((size_t)b * NTILE + t) * QLQ + q]);
#pragma unroll
    for (int s = 16; s > 0; s >>= 1)
        m += __shfl_xor_sync(0xFFFFFFFFu, m, s);
    if (q == 0) out[b] = m;
}

// ---------------- launch ----------------
extern "C" void kernel_launch(void* const* d_in, const int* in_sizes, int n_in,
                              void* d_out, int out_size) {
    const float* Q_emb = (const float*)d_in[0];
    const float* D_emb = (const float*)d_in[1];
    const int*   ids   = (const int*)d_in[2];
    const int*   attn  = (const int*)d_in[3];
    const float* W     = (const float*)d_in[4];
    float* out = (float*)d_out;

    cudaFuncSetAttribute(k_qproj,  cudaFuncAttributeMaxDynamicSharedMemorySize, SMEM_QP);
    cudaFuncSetAttribute(k_dscore, cudaFuncAttributeMaxDynamicSharedMemorySize, SMEM_DS);

    k_prep<<<(DIMD * HH + 255) / 256, 256>>>(W);
    k_qproj<<<BB, NTHREADS, SMEM_QP>>>(Q_emb);
    k_dscore<<<dim3(NTILE, BB), NTHREADS, SMEM_DS>>>(D_emb, ids, attn);
    k_final<<<BB, 32>>>(out);
}

// round 14
// speedup vs baseline: 1.1467x; 1.0690x over previous
#include <cuda_runtime.h>
#include <cuda_bf16.h>
#include <cstdint>

// ---------------- problem constants ----------------
#define BB    128
#define QLQ   32
#define DLD   1024
#define HH    768
#define DIMD  128
#define KC    64          // K elements per chunk (k_dscore mainloop)
#define NCHUNK 12         // 768 / 64
#define NTILE 8           // 1024 / 128
#define NEGV  (-100000.0f)
#define NTHREADS 512
#define QSTEP (6.0f / 127.0f)
#define QINV  (127.0f / 6.0f)

// strides
#define STR8  80          // int8 stage tiles: 64 K-bytes + 16 pad (bank-walk +20 words/row)
#define STRD  136         // D/Q bf16 tiles (128 cols + 8 pad)
#define STRK  136         // k_qproj stage tiles (128 K-cols + 8 pad)

// k_dscore smem layout (byte offsets) — THREE int8 stages of (A,W)
#define OFF_S0A  0u                    // 128 x STR8 = 10240
#define OFF_S0W  10240u
#define OFF_S1A  20480u
#define OFF_S1W  30720u
#define OFF_S2A  40960u
#define OFF_S2W  51200u                // stages end 61440
#define OFF_D    0u                    // D tile 128 x STRD bf16 = 34816 (overlays S0+S1, post-mainloop)
#define OFF_Q    61440u                // 32 x STRD bf16 = 8704  (end 70144)
#define OFF_N    70144u                // 128 x 4 float  = 2048  (end 72192)
#define OFF_R    72192u                // 8 x 32 float   = 1024  (end 73216)
#define OFF_SC   73216u                // 128 float col scales   (end 73728)
#define SMEM_DS  73728

// k_qproj smem layout (unchanged from R12, bf16)
#define QP_S0A   0u
#define QP_S0W   8704u
#define QP_S1A   43520u
#define QP_S1W   52224u
#define QP_N     87040u
#define SMEM_QP  88064

// ---------------- device scratch ----------------
__device__ __align__(16) __nv_bfloat16 g_Wb[DIMD * HH];          // bf16 W (k_qproj)
__device__ __align__(16) signed char   g_Wi8[DIMD * HH];         // int8 W (k_dscore)
__device__ float g_wscale[DIMD];
__device__ __align__(16) __nv_bfloat16 g_Qb[BB * QLQ * DIMD];
__device__ float g_part[BB * NTILE * QLQ];

// ---------------- helpers ----------------
static __device__ __forceinline__ uint32_t smem_u32(const void* p) {
    uint32_t a;
    asm("{ .reg .u64 t; cvta.to.shared.u64 t, %1; cvt.u32.u64 %0, t; }"
        : "=r"(a) : "l"(p));
    return a;
}
static __device__ __forceinline__ void ldsm_x4(uint32_t (&r)[4], uint32_t addr) {
    asm volatile("ldmatrix.sync.aligned.m8n8.x4.shared.b16 {%0,%1,%2,%3}, [%4];"
                 : "=r"(r[0]), "=r"(r[1]), "=r"(r[2]), "=r"(r[3]) : "r"(addr));
}
static __device__ __forceinline__ void mma_bf16(float (&d)[4], const uint32_t (&a)[4],
                                                const uint32_t* b) {
    asm volatile("mma.sync.aligned.m16n8k16.row.col.f32.bf16.bf16.f32 "
                 "{%0,%1,%2,%3}, {%4,%5,%6,%7}, {%8,%9}, {%0,%1,%2,%3};"
                 : "+f"(d[0]), "+f"(d[1]), "+f"(d[2]), "+f"(d[3])
                 : "r"(a[0]), "r"(a[1]), "r"(a[2]), "r"(a[3]), "r"(b[0]), "r"(b[1]));
}
static __device__ __forceinline__ void mma_s8(int (&d)[4], const uint32_t (&a)[4],
                                              uint32_t b0, uint32_t b1) {
    asm volatile("mma.sync.aligned.m16n8k32.row.col.s32.s8.s8.s32 "
                 "{%0,%1,%2,%3}, {%4,%5,%6,%7}, {%8,%9}, {%0,%1,%2,%3};"
                 : "+r"(d[0]), "+r"(d[1]), "+r"(d[2]), "+r"(d[3])
                 : "r"(a[0]), "r"(a[1]), "r"(a[2]), "r"(a[3]), "r"(b0), "r"(b1));
}
static __device__ __forceinline__ uint32_t packbf2(float lo, float hi) {
    __nv_bfloat162 v = __floats2bfloat162_rn(lo, hi);
    return *reinterpret_cast<uint32_t*>(&v);
}
static __device__ __forceinline__ uint32_t quant4(float4 v) {
    int i0 = __float2int_rn(v.x * QINV);
    int i1 = __float2int_rn(v.y * QINV);
    int i2 = __float2int_rn(v.z * QINV);
    int i3 = __float2int_rn(v.w * QINV);
    uint32_t t, r;
    asm("cvt.pack.sat.s8.s32.b32 %0, %1, %2, 0;" : "=r"(t) : "r"(i3), "r"(i2));
    asm("cvt.pack.sat.s8.s32.b32 %0, %1, %2, %3;" : "=r"(r) : "r"(i1), "r"(i0), "r"(t));
    return r;
}
static __device__ __forceinline__ void cp16(uint32_t dst, const void* src) {
    asm volatile("cp.async.cg.shared.global [%0], [%1], 16;"
                 :: "r"(dst), "l"(src) : "memory");
}
#define CP_COMMIT() asm volatile("cp.async.commit_group;" ::: "memory")
#define CP_WAIT(n)  asm volatile("cp.async.wait_group %0;" :: "n"(n) : "memory")

static __device__ __forceinline__ void sts128(uint32_t dst, uint32_t a, uint32_t b,
                                              uint32_t c, uint32_t d) {
    asm volatile("st.shared.v4.b32 [%0], {%1, %2, %3, %4};"
                 :: "r"(dst), "r"(a), "r"(b), "r"(c), "r"(d) : "memory");
}
// quantize+stage 16 fp32 -> 16 s8 (one STS.128)
static __device__ __forceinline__ void stage_A8(uint32_t dst, const float4 (&af)[4]) {
    sts128(dst, quant4(af[0]), quant4(af[1]), quant4(af[2]), quant4(af[3]));
}

// ---------------- kernel 0a: W -> bf16 ----------------
__global__ void k_prep(const float* __restrict__ W) {
    int i = blockIdx.x * blockDim.x + threadIdx.x;
    if (i < DIMD * HH) g_Wb[i] = __float2bfloat16(W[i]);
}

// ---------------- kernel 0b: W -> int8 with per-row scale ----------------
__global__ void k_prepW(const float* __restrict__ W) {
    __shared__ float red[8];
    const int d = blockIdx.x, tid = threadIdx.x;   // 256 threads
    float mx = 0.f;
    for (int k = tid; k < HH; k += 256) mx = fmaxf(mx, fabsf(W[d * HH + k]));
#pragma unroll
    for (int s = 16; s > 0; s >>= 1) mx = fmaxf(mx, __shfl_xor_sync(0xFFFFFFFFu, mx, s));
    if ((tid & 31) == 0) red[tid >> 5] = mx;
    __syncthreads();
    if (tid == 0) {
        float m = red[0];
#pragma unroll
        for (int i = 1; i < 8; ++i) m = fmaxf(m, red[i]);
        red[0] = fmaxf(m, 1e-20f);
    }
    __syncthreads();
    const float smax = red[0];
    const float inv = 127.f / smax;
    for (int k = tid; k < HH; k += 256) {
        int q = __float2int_rn(W[d * HH + k] * inv);
        q = max(-127, min(127, q));
        g_Wi8[d * HH + k] = (signed char)q;
    }
    if (tid == 0) g_wscale[d] = smax * (1.f / 127.f);
}

// ---------------- kernel 1: Q projection (bf16, unchanged from R12) ----------------
__global__ void __launch_bounds__(NTHREADS) k_qproj(const float* __restrict__ Q_emb) {
    extern __shared__ char dyn[];
    uint32_t sb = smem_u32(dyn);
    const int tid = threadIdx.x, lane = tid & 31, w = tid >> 5;
    const int wmq = w & 1, wnq = w >> 1;
    const int b = blockIdx.x;

    const float* a_rows = Q_emb + (size_t)b * QLQ * HH;
    const int lrq = tid >> 4, jq = tid & 15;
    const float* aptr = a_rows + (size_t)lrq * HH + jq * 8;
    const uint32_t stOA = (uint32_t)(lrq * STRK + jq * 8) * 2;
    const int lrw = tid >> 2, jw = tid & 3;
    const __nv_bfloat16* wsrc = g_Wb + (size_t)lrw * HH + jw * 32;
    const uint32_t stOW = (uint32_t)(lrw * STRK) * 2 + (uint32_t)jw * 64;

    const uint32_t sA[2] = {sb + QP_S0A, sb + QP_S1A};
    const uint32_t sW[2] = {sb + QP_S0W, sb + QP_S1W};
    const uint32_t ldAo = (uint32_t)((wmq * 16 + (lane & 15)) * STRK + (lane >> 4) * 8) * 2;
    const uint32_t ldBo = (uint32_t)((wnq * 16 + ((lane >> 4) & 1) * 8 + (lane & 7)) * STRK
                                     + ((lane >> 3) & 1) * 8) * 2;

    float4 af2[2];
    af2[0] = *(const float4*)(aptr);
    af2[1] = *(const float4*)(aptr + 4);
    sts128(sA[0] + stOA, packbf2(af2[0].x, af2[0].y), packbf2(af2[0].z, af2[0].w),
           packbf2(af2[1].x, af2[1].y), packbf2(af2[1].z, af2[1].w));
#pragma unroll
    for (int jj = 0; jj < 4; ++jj) cp16(sW[0] + stOW + jj * 16u, wsrc + jj * 8);
    CP_COMMIT();
    af2[0] = *(const float4*)(aptr + 128);
    af2[1] = *(const float4*)(aptr + 128 + 4);
    CP_WAIT(0);
    __syncthreads();

    float acc[2][4] = {};
    for (int kc = 0; kc < 6; ++kc) {
        const int cur = kc & 1;
        if (kc + 1 < 6) {
            const int nxt = cur ^ 1;
            sts128(sA[nxt] + stOA,
                   packbf2(af2[0].x, af2[0].y), packbf2(af2[0].z, af2[0].w),
                   packbf2(af2[1].x, af2[1].y), packbf2(af2[1].z, af2[1].w));
            const __nv_bfloat16* wp = wsrc + (kc + 1) * 128;
#pragma unroll
            for (int jj = 0; jj < 4; ++jj) cp16(sW[nxt] + stOW + jj * 16u, wp + jj * 8);
            CP_COMMIT();
            if (kc + 2 < 6) {
                af2[0] = *(const float4*)(aptr + (kc + 2) * 128);
                af2[1] = *(const float4*)(aptr + (kc + 2) * 128 + 4);
            }
        }
#pragma unroll
        for (int ks = 0; ks < 8; ++ks) {
            uint32_t afr[4], bfr[4];
            ldsm_x4(afr, sA[cur] + ldAo + (uint32_t)(ks * 16) * 2);
            ldsm_x4(bfr, sW[cur] + ldBo + (uint32_t)(ks * 16) * 2);
            mma_bf16(acc[0], afr, bfr);
            mma_bf16(acc[1], afr, bfr + 2);
        }
        CP_WAIT(0);
        __syncthreads();
    }

    float* nrm = (float*)(dyn + QP_N);
#pragma unroll
    for (int rs = 0; rs < 2; ++rs) {
        int gr = wmq * 16 + rs * 8 + (lane >> 2);
        float s = 0.f;
#pragma unroll
        for (int nt = 0; nt < 2; ++nt) {
            float x = acc[nt][rs * 2], y = acc[nt][rs * 2 + 1];
            s = fmaf(x, x, fmaf(y, y, s));
        }
        s += __shfl_xor_sync(0xFFFFFFFFu, s, 1);
        s += __shfl_xor_sync(0xFFFFFFFFu, s, 2);
        if ((lane & 3) == 0) nrm[gr * 8 + wnq] = s;
    }
    __syncthreads();
    if (tid < 32) {
        float s = 0.f;
#pragma unroll
        for (int k = 0; k < 8; ++k) s += nrm[tid * 8 + k];
        nrm[tid * 8] = rsqrtf(fmaxf(s, 1e-24f));
    }
    __syncthreads();
#pragma unroll
    for (int rs = 0; rs < 2; ++rs) {
        int gr = wmq * 16 + rs * 8 + (lane >> 2);
        float iv = nrm[gr * 8];
        size_t row = (size_t)b * QLQ + gr;
#pragma unroll
        for (int nt = 0; nt < 2; ++nt) {
            int col = wnq * 16 + nt * 8 + (lane & 3) * 2;
            *(uint32_t*)(g_Qb + row * DIMD + col) =
                packbf2(acc[nt][rs * 2] * iv, acc[nt][rs * 2 + 1] * iv);
        }
    }
}

// ---------------- int8 GEMM1 mainloop (3-stage, KC=64, m16n8k32) ----------------
static __device__ __forceinline__ void gemm1_i8(const float* __restrict__ a_rows,
                                                uint32_t sb,
                                                int (&acc)[2][4][4], int tid) {
    const int lane = tid & 31, w = tid >> 5;
    const int wm = w & 3, wn = w >> 2;
    const int lr = tid >> 2;                    // 0..127 load row
    const int j4 = tid & 3;                     // 4 threads per row
    const float* aptr = a_rows + (size_t)lr * HH + j4 * 16;
    const signed char* wsrc = g_Wi8 + (size_t)lr * HH + j4 * 16;

    const uint32_t sA[3] = {sb + OFF_S0A, sb + OFF_S1A, sb + OFF_S2A};
    const uint32_t sW[3] = {sb + OFF_S0W, sb + OFF_S1W, sb + OFF_S2W};
    const uint32_t stO = (uint32_t)(lr * STR8 + j4 * 16);
    const uint32_t ldAo = (uint32_t)((wm * 32 + (lane & 15)) * STR8 + (lane >> 4) * 16);
    const uint32_t ldBo = (uint32_t)((wn * 32 + ((lane >> 3) & 1) * 8 + (lane & 7)) * STR8
                                     + ((lane >> 4) & 1) * 16);

    float4 af[4];
    // prologue: chunks 0,1 staged; chunk 2 in regs
#pragma unroll
    for (int i = 0; i < 4; ++i) af[i] = *(const float4*)(aptr + i * 4);
    stage_A8(sA[0] + stO, af);
    cp16(sW[0] + stO, wsrc);
    CP_COMMIT();
#pragma unroll
    for (int i = 0; i < 4; ++i) af[i] = *(const float4*)(aptr + KC + i * 4);
    stage_A8(sA[1] + stO, af);
    cp16(sW[1] + stO, wsrc + KC);
    CP_COMMIT();
#pragma unroll
    for (int i = 0; i < 4; ++i) af[i] = *(const float4*)(aptr + 2 * KC + i * 4);
    CP_WAIT(1);
    __syncthreads();

    for (int kc = 0; kc < NCHUNK; ++kc) {
        const int cur = kc % 3;
        if (kc + 2 < NCHUNK) {
            const int ns = (kc + 2) % 3;
            stage_A8(sA[ns] + stO, af);          // af = chunk kc+2
            cp16(sW[ns] + stO, wsrc + (kc + 2) * KC);
            CP_COMMIT();
            if (kc + 3 < NCHUNK) {
                const float* ap = aptr + (kc + 3) * KC;
#pragma unroll
                for (int i = 0; i < 4; ++i) af[i] = *(const float4*)(ap + i * 4);
            }
        }
        // MMA on stage cur: 2 k32-steps
#pragma unroll
        for (int ks = 0; ks < 2; ++ks) {
            uint32_t afr[2][4], bfr[2][4];
#pragma unroll
            for (int mt = 0; mt < 2; ++mt)
                ldsm_x4(afr[mt], sA[cur] + ldAo + (uint32_t)(mt * 16 * STR8 + ks * 32));
#pragma unroll
            for (int np = 0; np < 2; ++np)
                ldsm_x4(bfr[np], sW[cur] + ldBo + (uint32_t)(np * 16 * STR8 + ks * 32));
#pragma unroll
            for (int mt = 0; mt < 2; ++mt)
#pragma unroll
                for (int np = 0; np < 2; ++np) {
                    mma_s8(acc[mt][np * 2],     afr[mt], bfr[np][0], bfr[np][2]);
                    mma_s8(acc[mt][np * 2 + 1], afr[mt], bfr[np][1], bfr[np][3]);
                }
        }
        if (kc + 2 < NCHUNK) CP_WAIT(1); else CP_WAIT(0);
        __syncthreads();
    }
}

// ---------------- kernel 2: D projection (int8) + scoring ----------------
__global__ void __launch_bounds__(NTHREADS)
k_dscore(const float* __restrict__ D_emb,
         const int* __restrict__ doc_ids,
         const int* __restrict__ doc_attn) {
    extern __shared__ char dyn[];
    uint32_t sb = smem_u32(dyn);
    const int tid = threadIdx.x, lane = tid & 31, w = tid >> 5;
    const int wm = w & 3, wn = w >> 2;
    const int tile = blockIdx.x, b = blockIdx.y;

    // stage Q tile + per-column combined scales (disjoint from pipeline stages)
    for (int g = tid; g < 512; g += NTHREADS) {
        int qr = g >> 4, qc = (g & 15) * 8;
        uint4 v = *(const uint4*)(g_Qb + ((size_t)b * QLQ + qr) * DIMD + qc);
        *(uint4*)(dyn + OFF_Q + (qr * STRD + qc) * 2) = v;
    }
    float* csc = (float*)(dyn + OFF_SC);
    if (tid < 128) csc[tid] = QSTEP * g_wscale[tid];

    int acc[2][4][4] = {};
    gemm1_i8(D_emb + ((size_t)b * DLD + (size_t)tile * 128) * HH, sb, acc, tid);
    // gemm1 ends with __syncthreads: stage reads complete -> D overlay safe

    float* nrm = (float*)(dyn + OFF_N);
    const uint32_t sD = sb + OFF_D;
    // epilogue 1: dequant, row sq-sums, bf16 D tile
#pragma unroll
    for (int mt = 0; mt < 2; ++mt)
#pragma unroll
        for (int rs = 0; rs < 2; ++rs) {
            int gr = wm * 32 + mt * 16 + rs * 8 + (lane >> 2);
            float s = 0.f;
#pragma unroll
            for (int nt = 0; nt < 4; ++nt) {
                int col = wn * 32 + nt * 8 + (lane & 3) * 2;
                float x = (float)acc[mt][nt][rs * 2]     * csc[col];
                float y = (float)acc[mt][nt][rs * 2 + 1] * csc[col + 1];
                s = fmaf(x, x, fmaf(y, y, s));
                asm volatile("st.shared.b32 [%0], %1;"
                             :: "r"(sD + (uint32_t)(gr * STRD + col) * 2),
                                "r"(packbf2(x, y)) : "memory");
            }
            s += __shfl_xor_sync(0xFFFFFFFFu, s, 1);
            s += __shfl_xor_sync(0xFFFFFFFFu, s, 2);
            if ((lane & 3) == 0) nrm[gr * 4 + wn] = s;
        }
    __syncthreads();
    if (tid < 128) {
        float s = nrm[tid * 4] + nrm[tid * 4 + 1] + nrm[tid * 4 + 2] + nrm[tid * 4 + 3];
        nrm[tid * 4] = rsqrtf(fmaxf(s, 1e-24f));
    }
    __syncthreads();

    // GEMM2 (warps 0-7, bf16): [128 tokens x 32 queries]
    if (w < 8) {
        const uint32_t sQ = sb + OFF_Q;
        const uint32_t ldA2 = sD + (uint32_t)((w * 16 + (lane & 15)) * STRD
                                              + (lane >> 4) * 8) * 2;
        const uint32_t ldB2 = sQ + (uint32_t)((((lane >> 4) & 1) * 8 + (lane & 7)) * STRD
                                              + ((lane >> 3) & 1) * 8) * 2;
        float acc2[4][4] = {};
#pragma unroll
        for (int ks = 0; ks < 8; ++ks) {
            uint32_t afr[4];
            ldsm_x4(afr, ldA2 + (uint32_t)(ks * 16) * 2);
#pragma unroll
            for (int np = 0; np < 2; ++np) {
                uint32_t bfr[4];
                ldsm_x4(bfr, ldB2 + (uint32_t)(np * 16 * STRD + ks * 16) * 2);
                mma_bf16(acc2[np * 2],     afr, bfr);
                mma_bf16(acc2[np * 2 + 1], afr, bfr + 2);
            }
        }

        const int tb = b * DLD + tile * 128;
        const int r0 = w * 16 + (lane >> 2), r1 = r0 + 8;
        const float iv0 = nrm[r0 * 4], iv1 = nrm[r1 * 4];
        const int id0 = doc_ids[tb + r0], id1 = doc_ids[tb + r1];
        const int at0 = doc_attn[tb + r0], at1 = doc_attn[tb + r1];
        float colmax[8];
#pragma unroll
        for (int nt = 0; nt < 4; ++nt)
#pragma unroll
            for (int c = 0; c < 2; ++c) {
                float v0 = at0 ? (id0 ? fmaf(2.f * iv0, acc2[nt][c], -2.f) : -1.f) : NEGV;
                float v1 = at1 ? (id1 ? fmaf(2.f * iv1, acc2[nt][2 + c], -2.f) : -1.f) : NEGV;
                colmax[nt * 2 + c] = fmaxf(v0, v1);
            }
#pragma unroll
        for (int s = 4; s < 32; s <<= 1)
#pragma unroll
            for (int j = 0; j < 8; ++j)
                colmax[j] = fmaxf(colmax[j], __shfl_xor_sync(0xFFFFFFFFu, colmax[j], s));

        float* red = (float*)(dyn + OFF_R);
        if (lane < 4)
#pragma unroll
            for (int nt = 0; nt < 4; ++nt)
#pragma unroll
                for (int c = 0; c < 2; ++c)
                    red[w * 32 + nt * 8 + lane * 2 + c] = colmax[nt * 2 + c];
    }
    __syncthreads();
    if (tid < 32) {
        float* red = (float*)(dyn + OFF_R);
        float m = -3.0e38f;
#pragma unroll
        for (int ww = 0; ww < 8; ++ww) m = fmaxf(m, red[ww * 32 + tid]);
        g_part[((size_t)b * NTILE + tile) * QLQ + tid] = m;
    }
}

// ---------------- kernel 3: combine tiles -> out[B] ----------------
__global__ void k_final(float* __restrict__ out) {
    int b = blockIdx.x, q = threadIdx.x;
    float m = -3.0e38f;
#pragma unroll
    for (int t = 0; t < NTILE; ++t)
        m = fmaxf(m, g_part[((size_t)b * NTILE + t) * QLQ + q]);
#pragma unroll
    for (int s = 16; s > 0; s >>= 1)
        m += __shfl_xor_sync(0xFFFFFFFFu, m, s);
    if (q == 0) out[b] = m;
}

// ---------------- launch ----------------
extern "C" void kernel_launch(void* const* d_in, const int* in_sizes, int n_in,
                              void* d_out, int out_size) {
    const float* Q_emb = (const float*)d_in[0];
    const float* D_emb = (const float*)d_in[1];
    const int*   ids   = (const int*)d_in[2];
    const int*   attn  = (const int*)d_in[3];
    const float* W     = (const float*)d_in[4];
    float* out = (float*)d_out;

    cudaFuncSetAttribute(k_qproj,  cudaFuncAttributeMaxDynamicSharedMemorySize, SMEM_QP);
    cudaFuncSetAttribute(k_dscore, cudaFuncAttributeMaxDynamicSharedMemorySize, SMEM_DS);

    k_prep<<<(DIMD * HH + 255) / 256, 256>>>(W);
    k_prepW<<<DIMD, 256>>>(W);
    k_qproj<<<BB, NTHREADS, SMEM_QP>>>(Q_emb);
    k_dscore<<<dim3(NTILE, BB), NTHREADS, SMEM_DS>>>(D_emb, ids, attn);
    k_final<<<BB, 32>>>(out);
}